// round 2
// baseline (speedup 1.0000x reference)
#include <cuda_runtime.h>

// ---------------- problem constants (fixed shapes) ----------------
#define C_CLASSES   12
#define LOG_DHW     20                    // d*h*w = 64*128*128 = 2^20
#define DHW         (1u << LOG_DHW)
#define NPIX        (2u * DHW)            // n * d*h*w = 2,097,152
#define MIN_KEPT_K  10000u
#define IGNORE_LBL  255
#define INF_BITS    0x7F800000u
#define THRESH_F    0.9f

// ---------------- device scratch (no runtime allocation) ----------------
__device__ unsigned int g_prob_bits[NPIX];     // prob as monotone uint bits; INF for invalid
__device__ float        g_nll[NPIX];           // -log p at label (0 for invalid)
__device__ unsigned int g_hist[4096];          // [0:1024) L0, [1024:3072) L1, [3072:4096) L2
__device__ unsigned int g_state[8];
__device__ double       g_sum;

enum { S_B0 = 0, S_R1 = 1, S_B1 = 2, S_R2 = 3, S_KEEPALL = 4, S_TH = 5, S_CNT = 6 };

// ---------------- zero scratch ----------------
__global__ void zero_kernel() {
    int t = blockIdx.x * blockDim.x + threadIdx.x;
    if (t < 4096) g_hist[t] = 0u;
    if (t < 8)    g_state[t] = 0u;
    if (t == 0)   g_sum = 0.0;
}

// ---------------- per-pixel CE ----------------
__device__ __forceinline__ void pixel_ce(const float v[C_CLASSES], int l,
                                         unsigned int& bits, float& nll) {
    float m = v[0];
#pragma unroll
    for (int c = 1; c < C_CLASSES; c++) m = fmaxf(m, v[c]);
    float sum = 0.f;
    float xl  = 0.f;
#pragma unroll
    for (int c = 0; c < C_CLASSES; c++) {
        sum += __expf(v[c] - m);
        if (c == l) xl = v[c];
    }
    float lse = m + __logf(sum);
    float lp  = xl - lse;
    if (l == IGNORE_LBL) {
        bits = INF_BITS;   // invalid -> +inf, sorts to the end exactly like reference
        nll  = 0.f;
    } else {
        bits = __float_as_uint(__expf(lp));   // prob in [0,1]: uint bits are order-preserving
        nll  = -lp;
    }
}

// ---------------- pass 1: compute prob/nll + level-0 histogram ----------------
#define CB_BLOCKS  1024
#define CB_THREADS 256

__global__ void __launch_bounds__(CB_THREADS)
compute_kernel(const float* __restrict__ pred, const int* __restrict__ tgt) {
    __shared__ unsigned int sh[1024];
    for (int i = threadIdx.x; i < 1024; i += CB_THREADS) sh[i] = 0u;
    __syncthreads();

    const unsigned stride_px = CB_BLOCKS * CB_THREADS * 4u;
    for (unsigned p = (blockIdx.x * CB_THREADS + threadIdx.x) * 4u; p < NPIX; p += stride_px) {
        unsigned n = p >> LOG_DHW;
        unsigned s = p & (DHW - 1u);
        const float* base = pred + (((size_t)n * C_CLASSES) << LOG_DHW) + s;

        float4 x[C_CLASSES];
#pragma unroll
        for (int c = 0; c < C_CLASSES; c++)
            x[c] = *(const float4*)(base + ((size_t)c << LOG_DHW));

        int4 lab = ((const int4*)tgt)[p >> 2];   // target is int32 (jax x64 disabled)

        float v[C_CLASSES];
        uint4  pb;
        float4 nl;
#pragma unroll
        for (int c = 0; c < C_CLASSES; c++) v[c] = x[c].x;
        pixel_ce(v, lab.x, pb.x, nl.x);
#pragma unroll
        for (int c = 0; c < C_CLASSES; c++) v[c] = x[c].y;
        pixel_ce(v, lab.y, pb.y, nl.y);
#pragma unroll
        for (int c = 0; c < C_CLASSES; c++) v[c] = x[c].z;
        pixel_ce(v, lab.z, pb.z, nl.z);
#pragma unroll
        for (int c = 0; c < C_CLASSES; c++) v[c] = x[c].w;
        pixel_ce(v, lab.w, pb.w, nl.w);

        ((uint4*)g_prob_bits)[p >> 2] = pb;
        ((float4*)g_nll)[p >> 2]      = nl;

        atomicAdd(&sh[pb.x >> 21], 1u);
        atomicAdd(&sh[pb.y >> 21], 1u);
        atomicAdd(&sh[pb.z >> 21], 1u);
        atomicAdd(&sh[pb.w >> 21], 1u);
    }
    __syncthreads();
    for (int i = threadIdx.x; i < 1024; i += CB_THREADS) {
        unsigned c = sh[i];
        if (c) atomicAdd(&g_hist[i], c);
    }
}

// ---------------- level-1 / level-2 refinement histograms ----------------
#define HB_BLOCKS (NPIX / 4 / 256)   // 2048
__global__ void __launch_bounds__(256) hist1_kernel() {
    __shared__ unsigned int sh[2048];
    for (int i = threadIdx.x; i < 2048; i += 256) sh[i] = 0u;
    __syncthreads();
    unsigned b0  = g_state[S_B0];
    unsigned tid = blockIdx.x * 256 + threadIdx.x;
    uint4 pb = ((const uint4*)g_prob_bits)[tid];
    if ((pb.x >> 21) == b0) atomicAdd(&sh[(pb.x >> 10) & 0x7FFu], 1u);
    if ((pb.y >> 21) == b0) atomicAdd(&sh[(pb.y >> 10) & 0x7FFu], 1u);
    if ((pb.z >> 21) == b0) atomicAdd(&sh[(pb.z >> 10) & 0x7FFu], 1u);
    if ((pb.w >> 21) == b0) atomicAdd(&sh[(pb.w >> 10) & 0x7FFu], 1u);
    __syncthreads();
    for (int i = threadIdx.x; i < 2048; i += 256) {
        unsigned c = sh[i];
        if (c) atomicAdd(&g_hist[1024 + i], c);
    }
}

__global__ void __launch_bounds__(256) hist2_kernel() {
    __shared__ unsigned int sh[1024];
    for (int i = threadIdx.x; i < 1024; i += 256) sh[i] = 0u;
    __syncthreads();
    unsigned top22 = (g_state[S_B0] << 11) | g_state[S_B1];
    unsigned tid   = blockIdx.x * 256 + threadIdx.x;
    uint4 pb = ((const uint4*)g_prob_bits)[tid];
    if ((pb.x >> 10) == top22) atomicAdd(&sh[pb.x & 0x3FFu], 1u);
    if ((pb.y >> 10) == top22) atomicAdd(&sh[pb.y & 0x3FFu], 1u);
    if ((pb.z >> 10) == top22) atomicAdd(&sh[pb.z & 0x3FFu], 1u);
    if ((pb.w >> 10) == top22) atomicAdd(&sh[pb.w & 0x3FFu], 1u);
    __syncthreads();
    for (int i = threadIdx.x; i < 1024; i += 256) {
        unsigned c = sh[i];
        if (c) atomicAdd(&g_hist[3072 + i], c);
    }
}

// ---------------- single-block k-th locate inside a histogram ----------------
template <int NBINS>
__device__ __forceinline__ void find_kth(const unsigned int* __restrict__ hist, unsigned k,
                                         unsigned* bin_out, unsigned* rank_out) {
    __shared__ unsigned int partial[1024];
    __shared__ unsigned int res[2];
    const int t = threadIdx.x;
    constexpr int PER = NBINS / 1024;   // 1 or 2
    unsigned h[PER];
    unsigned local = 0;
#pragma unroll
    for (int i = 0; i < PER; i++) { h[i] = hist[t * PER + i]; local += h[i]; }
    partial[t] = local;
    __syncthreads();
    for (int off = 1; off < 1024; off <<= 1) {
        unsigned add = (t >= off) ? partial[t - off] : 0u;
        __syncthreads();
        partial[t] += add;
        __syncthreads();
    }
    unsigned incl = partial[t];
    unsigned excl = incl - local;
    if (k >= excl && k < incl) {
        unsigned run = excl;
        bool found = false;
#pragma unroll
        for (int i = 0; i < PER; i++) {
            if (!found) {
                if (k < run + h[i]) { res[0] = t * PER + i; res[1] = k - run; found = true; }
                else run += h[i];
            }
        }
    }
    __syncthreads();
    *bin_out  = res[0];
    *rank_out = res[1];
}

__global__ void __launch_bounds__(1024) select0_kernel() {
    unsigned inv       = g_hist[1020];               // only exact +inf lands in bin 1020
    unsigned num_valid = NPIX - inv;
    unsigned keep_all  = (MIN_KEPT_K >= num_valid) ? 1u : 0u;
    unsigned mk        = (MIN_KEPT_K < num_valid) ? MIN_KEPT_K : num_valid;
    unsigned k         = (mk > 0u) ? (mk - 1u) : 0u;
    unsigned bin, rank;
    find_kth<1024>(g_hist, k, &bin, &rank);
    if (threadIdx.x == 0) {
        g_state[S_B0] = bin;
        g_state[S_R1] = rank;
        g_state[S_KEEPALL] = keep_all;
    }
}

__global__ void __launch_bounds__(1024) select1_kernel() {
    unsigned bin, rank;
    find_kth<2048>(g_hist + 1024, g_state[S_R1], &bin, &rank);
    if (threadIdx.x == 0) { g_state[S_B1] = bin; g_state[S_R2] = rank; }
}

__global__ void __launch_bounds__(1024) select2_kernel() {
    unsigned bin, rank;
    find_kth<1024>(g_hist + 3072, g_state[S_R2], &bin, &rank);
    if (threadIdx.x == 0) {
        unsigned th_bits = (g_state[S_B0] << 21) | (g_state[S_B1] << 10) | bin;
        float th = fmaxf(__uint_as_float(th_bits), THRESH_F);
        g_state[S_TH] = __float_as_uint(th);
    }
}

// ---------------- final masked reduction ----------------
__global__ void __launch_bounds__(256) reduce_kernel() {
    unsigned tid = blockIdx.x * 256 + threadIdx.x;
    float    th       = __uint_as_float(g_state[S_TH]);
    unsigned keep_all = g_state[S_KEEPALL];

    uint4  pb = ((const uint4*)g_prob_bits)[tid];
    float4 nl = ((const float4*)g_nll)[tid];

    float    s   = 0.f;
    unsigned cnt = 0u;
    {
        if (pb.x != INF_BITS && (keep_all || __uint_as_float(pb.x) <= th)) { s += nl.x; cnt++; }
        if (pb.y != INF_BITS && (keep_all || __uint_as_float(pb.y) <= th)) { s += nl.y; cnt++; }
        if (pb.z != INF_BITS && (keep_all || __uint_as_float(pb.z) <= th)) { s += nl.z; cnt++; }
        if (pb.w != INF_BITS && (keep_all || __uint_as_float(pb.w) <= th)) { s += nl.w; cnt++; }
    }
#pragma unroll
    for (int off = 16; off > 0; off >>= 1) {
        s   += __shfl_down_sync(0xFFFFFFFFu, s, off);
        cnt += __shfl_down_sync(0xFFFFFFFFu, cnt, off);
    }
    __shared__ float    ss[8];
    __shared__ unsigned sc[8];
    int w = threadIdx.x >> 5;
    if ((threadIdx.x & 31) == 0) { ss[w] = s; sc[w] = cnt; }
    __syncthreads();
    if (threadIdx.x == 0) {
        float    S  = 0.f;
        unsigned Ct = 0u;
#pragma unroll
        for (int i = 0; i < 8; i++) { S += ss[i]; Ct += sc[i]; }
        atomicAdd(&g_sum, (double)S);
        atomicAdd(&g_state[S_CNT], Ct);
    }
}

__global__ void finalize_kernel(float* __restrict__ out) {
    unsigned cnt = g_state[S_CNT];
    float denom  = (float)((cnt > 0u) ? cnt : 1u);
    out[0] = (float)(g_sum / (double)denom);
}

// ---------------- launch ----------------
extern "C" void kernel_launch(void* const* d_in, const int* in_sizes, int n_in,
                              void* d_out, int out_size) {
    const float* pred = (const float*)d_in[0];
    const int*   tgt  = (const int*)d_in[1];
    float*       out  = (float*)d_out;

    zero_kernel<<<4, 1024>>>();
    compute_kernel<<<CB_BLOCKS, CB_THREADS>>>(pred, tgt);
    select0_kernel<<<1, 1024>>>();
    hist1_kernel<<<HB_BLOCKS, 256>>>();
    select1_kernel<<<1, 1024>>>();
    hist2_kernel<<<HB_BLOCKS, 256>>>();
    select2_kernel<<<1, 1024>>>();
    reduce_kernel<<<HB_BLOCKS, 256>>>();
    finalize_kernel<<<1, 1>>>(out);
}